// round 12
// baseline (speedup 1.0000x reference)
#include <cuda_runtime.h>
#include <cuda_fp16.h>
#include <cstdint>
#include <math.h>

// ---------------------------------------------------------------------------
// Attention2D (b=4, c=512, hw=4096) — Round 12.
// Scores and PV GEMMs moved to FP8 e4m3 mma (m16n8k32, fp32 acc): Q/K/V/P
// stored e4m3 (output is residual-dominated -> ~300x error dilution, fp8 is
// safe). QK/V convs stay fp16-acc but emit fp8. Final conv fp32-acc.
// ---------------------------------------------------------------------------

#define B_  4
#define C_  512
#define HW_ 4096
#define NG_ 32
#define CPG_ (C_ / NG_)
#define GRP_ELEMS (CPG_ * HW_)

__device__ __align__(256) __half  g_xt [(size_t)B_ * HW_ * C_];
__device__ __align__(256) uint8_t g_qk8[(size_t)B_ * HW_ * 1024];   // 16 MB
__device__ __align__(256) uint8_t g_v8 [(size_t)B_ * C_ * HW_];     //  8 MB
__device__ __align__(256) uint8_t g_st8[(size_t)B_ * HW_ * HW_];    // 64 MB
__device__ __align__(256) __half  g_ot [(size_t)B_ * HW_ * C_];
__device__ __align__(256) __half  g_wh [4][(size_t)C_ * C_];
__device__ float  g_bqk[1024];
__device__ float  g_rsum[B_ * HW_];

// ================= weight convert + bias cat + rsum zero ==================
__global__ __launch_bounds__(256) void prep_kernel(
    const float* __restrict__ w0, const float* __restrict__ w1,
    const float* __restrict__ w2, const float* __restrict__ w3,
    __half* __restrict__ o,
    const float* __restrict__ bq, const float* __restrict__ bk,
    float* __restrict__ bqk, float* __restrict__ rs)
{
    const int n4 = C_ * C_ / 4;
    int i = blockIdx.x * blockDim.x + threadIdx.x;
    if (i < 4 * n4) {
        int w = i >> 16;
        int e = i & (n4 - 1);
        const float* src = (w == 0) ? w0 : (w == 1) ? w1 : (w == 2) ? w2 : w3;
        float4 v = reinterpret_cast<const float4*>(src)[e];
        __half2 h0 = __floats2half2_rn(v.x, v.y);
        __half2 h1 = __floats2half2_rn(v.z, v.w);
        __half2* dst = reinterpret_cast<__half2*>(o + (size_t)w * C_ * C_);
        dst[2 * e] = h0;
        dst[2 * e + 1] = h1;
    } else if (i < 4 * n4 + 1024) {
        int ii = i - 4 * n4;
        bqk[ii] = (ii < C_) ? bq[ii] : bk[ii - C_];
    } else {
        int jj = i - 4 * n4 - 1024;
        if (jj < B_ * HW_) rs[jj] = 0.f;
    }
}

// ================= GroupNorm fused: stats + apply + transpose ==============
#define TP 514
__global__ __launch_bounds__(256) void gn_fused(
    const float* __restrict__ x, const float* __restrict__ gamma,
    const float* __restrict__ beta, __half* __restrict__ xt)
{
    __shared__ float T[CPG_][TP];
    __shared__ float rs[8], rss[8];
    __shared__ float sc[CPG_], sh[CPG_];

    int b = blockIdx.x / NG_, g = blockIdx.x % NG_;
    size_t base = ((size_t)b * C_ + (size_t)g * CPG_) * HW_;
    int t = threadIdx.x;

    const float4* x4 = reinterpret_cast<const float4*>(x + base);
    float s = 0.f, ss = 0.f;
    for (int i = t; i < GRP_ELEMS / 4; i += 256) {
        float4 v = x4[i];
        s  += v.x + v.y + v.z + v.w;
        ss += v.x * v.x + v.y * v.y + v.z * v.z + v.w * v.w;
    }
    #pragma unroll
    for (int o = 16; o; o >>= 1) {
        s  += __shfl_xor_sync(0xffffffffu, s,  o);
        ss += __shfl_xor_sync(0xffffffffu, ss, o);
    }
    if ((t & 31) == 0) { rs[t >> 5] = s; rss[t >> 5] = ss; }
    __syncthreads();
    if (t < CPG_) {
        float ts = 0.f, tss = 0.f;
        #pragma unroll
        for (int i = 0; i < 8; i++) { ts += rs[i]; tss += rss[i]; }
        float inv_n = 1.0f / (float)GRP_ELEMS;
        float mu  = ts * inv_n;
        float var = tss * inv_n - mu * mu;
        float rstd = rsqrtf(var + 1e-6f);
        int c = g * CPG_ + t;
        float gm = gamma[c] * rstd;
        sc[t] = gm;
        sh[t] = beta[c] - mu * gm;
    }
    __syncthreads();

    size_t tb = (size_t)b * HW_ * C_ + (size_t)g * CPG_;
    for (int j0 = 0; j0 < HW_; j0 += 512) {
        #pragma unroll
        for (int i = 0; i < 32; i++) {
            int idx = i * 256 + t;
            int c = idx >> 9;
            int j = idx & 511;
            float v = x[base + (size_t)c * HW_ + j0 + j];
            T[c][j] = v * sc[c] + sh[c];
        }
        __syncthreads();
        #pragma unroll
        for (int i = 0; i < 16; i++) {
            int idx = i * 256 + t;
            int j  = idx >> 3;
            int cq = idx & 7;
            __half2 h = __floats2half2_rn(T[2 * cq][j], T[2 * cq + 1][j]);
            *reinterpret_cast<__half2*>(xt + tb + (size_t)(j0 + j) * C_ + 2 * cq) = h;
        }
        __syncthreads();
    }
}

// ========================= common GEMM pieces ==============================
#define BM 128
#define BN 128
#define NSTAGE 3
#define STAGE_B 16384u                     // 128 rows x 128 bytes
#define SMEM_SZ (NSTAGE * 2 * STAGE_B)     // 96 KB

__device__ __forceinline__ uint32_t smem_u32(const void* p) {
    uint32_t a;
    asm("{ .reg .u64 t; cvta.to.shared.u64 t, %1; cvt.u32.u64 %0, t; }"
        : "=r"(a) : "l"(p));
    return a;
}

__device__ __forceinline__ float fexp2(float x) {
    x = fmaxf(x, -120.f);
    float k = rintf(x);
    float r = x - k;
    float p = 0.0013333558f;
    p = fmaf(p, r, 0.0096181291f);
    p = fmaf(p, r, 0.0555041087f);
    p = fmaf(p, r, 0.2402265069f);
    p = fmaf(p, r, 0.6931471806f);
    p = fmaf(p, r, 1.0f);
    return p * __int_as_float(((int)k + 127) << 23);
}

// pack two f32 into e4m3x2 (lo = v0, hi = v1)
__device__ __forceinline__ uint16_t pack_e4m3(float v0, float v1) {
    uint16_t r;
    asm("cvt.rn.satfinite.e4m3x2.f32 %0, %1, %2;" : "=h"(r) : "f"(v1), "f"(v0));
    return r;
}

// generic 128-row x 128-byte tile loader (works for fp16 BK=64 and fp8 BK=128)
__device__ __forceinline__ void load_tile_b(
    uint32_t sdst, const uint8_t* __restrict__ src, long ld, int tid)
{
    #pragma unroll
    for (int i = 0; i < 8; i++) {
        int idx = tid + (i << 7);
        int r = idx >> 3;
        int c = idx & 7;
        uint32_t sw = (uint32_t)r * 128 + (uint32_t)((c ^ (r & 7)) << 4);
        asm volatile("cp.async.cg.shared.global [%0], [%1], 16;"
                     :: "r"(sdst + sw), "l"(src + (long)r * ld + (c << 4))
                     : "memory");
    }
}

#define LDSM4(r0, r1, r2, r3, a)                                           \
    asm volatile("ldmatrix.sync.aligned.m8n8.x4.shared.b16 {%0,%1,%2,%3}, [%4];" \
                 : "=r"(r0), "=r"(r1), "=r"(r2), "=r"(r3) : "r"(a))

#define MMA16816(acc, av, b0, b1)                                           \
    asm volatile(                                                           \
        "mma.sync.aligned.m16n8k16.row.col.f32.f16.f16.f32 "                \
        "{%0,%1,%2,%3}, {%4,%5,%6,%7}, {%8,%9}, {%0,%1,%2,%3};"             \
        : "+f"((acc)[0]), "+f"((acc)[1]), "+f"((acc)[2]), "+f"((acc)[3])    \
        : "r"((av)[0]), "r"((av)[1]), "r"((av)[2]), "r"((av)[3]),           \
          "r"(b0), "r"(b1))

#define MMA16816_H(acc, av, b0, b1)                                         \
    asm volatile(                                                           \
        "mma.sync.aligned.m16n8k16.row.col.f16.f16.f16.f16 "                \
        "{%0,%1}, {%2,%3,%4,%5}, {%6,%7}, {%0,%1};"                         \
        : "+r"((acc)[0]), "+r"((acc)[1])                                    \
        : "r"((av)[0]), "r"((av)[1]), "r"((av)[2]), "r"((av)[3]),           \
          "r"(b0), "r"(b1))

#define MMA16832_F8(acc, av, b0, b1)                                        \
    asm volatile(                                                           \
        "mma.sync.aligned.m16n8k32.row.col.f32.e4m3.e4m3.f32 "              \
        "{%0,%1,%2,%3}, {%4,%5,%6,%7}, {%8,%9}, {%0,%1,%2,%3};"             \
        : "+f"((acc)[0]), "+f"((acc)[1]), "+f"((acc)[2]), "+f"((acc)[3])    \
        : "r"((av)[0]), "r"((av)[1]), "r"((av)[2]), "r"((av)[3]),           \
          "r"(b0), "r"(b1))

// shared mainloop macro body (identical tile/LDSM schedule)
#define GEMM_MAINLOOP(MMA_OP, ACC)                                          \
    load_tile_b(sA[0], Ab, lda, tid);                                       \
    load_tile_b(sB[0], Bb, ldb, tid);                                       \
    asm volatile("cp.async.commit_group;");                                 \
    if (T > 1) {                                                            \
        load_tile_b(sA[1], Ab + KB, lda, tid);                              \
        load_tile_b(sB[1], Bb + KB, ldb, tid);                              \
    }                                                                       \
    asm volatile("cp.async.commit_group;");                                 \
    for (int t = 0; t < T; t++) {                                           \
        int cs = t % NSTAGE;                                                \
        asm volatile("cp.async.wait_group 1;");                             \
        __syncthreads();                                                    \
        if (t + 2 < T) {                                                    \
            int ns = (t + 2) % NSTAGE;                                      \
            load_tile_b(sA[ns], Ab + (size_t)(t + 2) * KB, lda, tid);       \
            load_tile_b(sB[ns], Bb + (size_t)(t + 2) * KB, ldb, tid);       \
        }                                                                   \
        asm volatile("cp.async.commit_group;");                             \
        _Pragma("unroll")                                                   \
        for (int ks = 0; ks < 4; ks++) {                                    \
            int ach = ks * 2 + a_cs;                                        \
            int bch = ks * 2 + b_cs;                                        \
            uint32_t b0[4], b1[4];                                          \
            {                                                               \
                uint32_t row = bRow;                                        \
                uint32_t addr = sB[cs] + row * 128                          \
                              + (uint32_t)((bch ^ (row & 7)) << 4);         \
                LDSM4(b0[0], b0[1], b0[2], b0[3], addr);                    \
            }                                                               \
            uint32_t a[4][4];                                               \
            _Pragma("unroll")                                               \
            for (int mt = 0; mt < 4; mt++) {                                \
                uint32_t row = aRow + mt * 16;                              \
                uint32_t addr = sA[cs] + row * 128                          \
                              + (uint32_t)((ach ^ (row & 7)) << 4);         \
                LDSM4(a[mt][0], a[mt][1], a[mt][2], a[mt][3], addr);        \
            }                                                               \
            _Pragma("unroll")                                               \
            for (int p = 0; p < 4; p++) {                                   \
                uint32_t* bc = (p & 1) ? b1 : b0;                           \
                uint32_t* bn = (p & 1) ? b0 : b1;                           \
                if (p < 3) {                                                \
                    uint32_t row = bRow + (p + 1) * 16;                     \
                    uint32_t addr = sB[cs] + row * 128                      \
                                  + (uint32_t)((bch ^ (row & 7)) << 4);     \
                    LDSM4(bn[0], bn[1], bn[2], bn[3], addr);                \
                }                                                           \
                _Pragma("unroll")                                           \
                for (int mt = 0; mt < 4; mt++) {                            \
                    MMA_OP(ACC[mt][2 * p],     a[mt], bc[0], bc[1]);        \
                    MMA_OP(ACC[mt][2 * p + 1], a[mt], bc[2], bc[3]);        \
                }                                                           \
            }                                                               \
        }                                                                   \
    }

// =============== fp32-acc fp16 GEMM (final conv: residual, fp32 out) =======
__global__ __launch_bounds__(128, 2) void mm_h(
    const __half* __restrict__ A, long lda_h, long asb,
    const __half* __restrict__ Bp, long ldb_h, long bsb,
    float* __restrict__ Cf, long ldc, long csb,
    const float* __restrict__ bias_m,
    const float* __restrict__ res, long rsb, float alpha, int T)
{
    extern __shared__ __half smem[];
    uint32_t sb = smem_u32(smem);
    uint32_t sA[NSTAGE], sB[NSTAGE];
    #pragma unroll
    for (int s = 0; s < NSTAGE; s++) {
        sA[s] = sb + (uint32_t)s * 2 * STAGE_B;
        sB[s] = sA[s] + STAGE_B;
    }
    const long KB = 128;          // bytes per K-chunk
    long lda = lda_h * 2, ldb = ldb_h * 2;

    int tid = threadIdx.x, lane = tid & 31, wid = tid >> 5;
    int wm = wid >> 1, wn = wid & 1;
    int bz = blockIdx.z;
    int m0 = blockIdx.y * BM, n0 = blockIdx.x * BN;

    const uint8_t* Ab = reinterpret_cast<const uint8_t*>(A + (size_t)bz * asb)
                      + (size_t)m0 * lda;
    const uint8_t* Bb = reinterpret_cast<const uint8_t*>(Bp + (size_t)bz * bsb)
                      + (size_t)n0 * ldb;

    float acc[4][8][4];
    #pragma unroll
    for (int i = 0; i < 4; i++)
        #pragma unroll
        for (int j = 0; j < 8; j++)
            #pragma unroll
            for (int k = 0; k < 4; k++) acc[i][j][k] = 0.f;

    int a_r  = (lane & 7) | (((lane >> 3) & 1) << 3);
    int a_cs = lane >> 4;
    int b_r  = (lane & 7) | (((lane >> 4) & 1) << 3);
    int b_cs = (lane >> 3) & 1;
    uint32_t aRow = (uint32_t)(wm * 64 + a_r);
    uint32_t bRow = (uint32_t)(wn * 64 + b_r);

    GEMM_MAINLOOP(MMA16816, acc)

    int mb = m0 + wm * 64;
    int nb = n0 + wn * 64;
    int r0 = lane >> 2, c0 = (lane & 3) * 2;
    float* Cfb = Cf + (size_t)bz * csb;
    const float* Rb = res + (size_t)bz * rsb;

    #pragma unroll
    for (int mt = 0; mt < 4; mt++) {
        #pragma unroll
        for (int h = 0; h < 2; h++) {
            int m = mb + mt * 16 + r0 + h * 8;
            float bmv = bias_m[m];
            #pragma unroll
            for (int nt = 0; nt < 8; nt++) {
                int n = nb + nt * 8 + c0;
                const float* rp = Rb + (size_t)m * ldc + n;
                float v0 = (acc[mt][nt][2 * h + 0] + bmv + rp[0]) * alpha;
                float v1 = (acc[mt][nt][2 * h + 1] + bmv + rp[1]) * alpha;
                *reinterpret_cast<float2*>(Cfb + (size_t)m * ldc + n) =
                    make_float2(v0, v1);
            }
        }
    }
}

// ========== fp16-acc GEMM, fp8 output (QK proj and V proj) =================
__global__ __launch_bounds__(128, 2) void mm_h16_o8(
    const __half* __restrict__ A, long lda_h, long asb,
    const __half* __restrict__ Bp, long ldb_h, long bsb,
    uint8_t* __restrict__ C8, long ldc, long csb,
    const float* __restrict__ bias_m, const float* __restrict__ bias_n,
    int T)
{
    extern __shared__ __half smem[];
    uint32_t sb = smem_u32(smem);
    uint32_t sA[NSTAGE], sB[NSTAGE];
    #pragma unroll
    for (int s = 0; s < NSTAGE; s++) {
        sA[s] = sb + (uint32_t)s * 2 * STAGE_B;
        sB[s] = sA[s] + STAGE_B;
    }
    const long KB = 128;
    long lda = lda_h * 2, ldb = ldb_h * 2;

    int tid = threadIdx.x, lane = tid & 31, wid = tid >> 5;
    int wm = wid >> 1, wn = wid & 1;
    int bz = blockIdx.z;
    int m0 = blockIdx.y * BM, n0 = blockIdx.x * BN;

    const uint8_t* Ab = reinterpret_cast<const uint8_t*>(A + (size_t)bz * asb)
                      + (size_t)m0 * lda;
    const uint8_t* Bb = reinterpret_cast<const uint8_t*>(Bp + (size_t)bz * bsb)
                      + (size_t)n0 * ldb;

    uint32_t acc[4][8][2];
    #pragma unroll
    for (int i = 0; i < 4; i++)
        #pragma unroll
        for (int j = 0; j < 8; j++) { acc[i][j][0] = 0u; acc[i][j][1] = 0u; }

    int a_r  = (lane & 7) | (((lane >> 3) & 1) << 3);
    int a_cs = lane >> 4;
    int b_r  = (lane & 7) | (((lane >> 4) & 1) << 3);
    int b_cs = (lane >> 3) & 1;
    uint32_t aRow = (uint32_t)(wm * 64 + a_r);
    uint32_t bRow = (uint32_t)(wn * 64 + b_r);

    GEMM_MAINLOOP(MMA16816_H, acc)

    int mb = m0 + wm * 64;
    int nb = n0 + wn * 64;
    int r0 = lane >> 2, c0 = (lane & 3) * 2;
    uint8_t* Cb = C8 + (size_t)bz * csb;

    #pragma unroll
    for (int mt = 0; mt < 4; mt++) {
        #pragma unroll
        for (int h = 0; h < 2; h++) {
            int m = mb + mt * 16 + r0 + h * 8;
            float bmv = bias_m ? bias_m[m] : 0.f;
            #pragma unroll
            for (int nt = 0; nt < 8; nt++) {
                int n = nb + nt * 8 + c0;
                float2 f = __half22float2(
                    *reinterpret_cast<__half2*>(&acc[mt][nt][h]));
                float v0 = f.x + bmv, v1 = f.y + bmv;
                if (bias_n) { v0 += bias_n[n]; v1 += bias_n[n + 1]; }
                *reinterpret_cast<uint16_t*>(Cb + (size_t)m * ldc + n) =
                    pack_e4m3(v0, v1);
            }
        }
    }
}

// ================= FP8 GEMM (scores emode=1, PV emode=2) ===================
__global__ __launch_bounds__(128, 2) void mm_f8(
    const uint8_t* __restrict__ A, long lda, long asb,
    const uint8_t* __restrict__ Bp, long ldb, long bsb,
    uint8_t* __restrict__ C8, __half* __restrict__ Ch, long ldc, long csb,
    float alpha, int T, float* __restrict__ rowsum, int emode)
{
    extern __shared__ __half smem[];
    uint32_t sb = smem_u32(smem);
    uint32_t sA[NSTAGE], sB[NSTAGE];
    #pragma unroll
    for (int s = 0; s < NSTAGE; s++) {
        sA[s] = sb + (uint32_t)s * 2 * STAGE_B;
        sB[s] = sA[s] + STAGE_B;
    }
    const long KB = 128;   // 128 fp8 per K-chunk

    int tid = threadIdx.x, lane = tid & 31, wid = tid >> 5;
    int wm = wid >> 1, wn = wid & 1;
    int bz = blockIdx.z;
    int m0 = blockIdx.y * BM, n0 = blockIdx.x * BN;

    const uint8_t* Ab = A + (size_t)bz * asb + (size_t)m0 * lda;
    const uint8_t* Bb = Bp + (size_t)bz * bsb + (size_t)n0 * ldb;

    float acc[4][8][4];
    #pragma unroll
    for (int i = 0; i < 4; i++)
        #pragma unroll
        for (int j = 0; j < 8; j++)
            #pragma unroll
            for (int k = 0; k < 4; k++) acc[i][j][k] = 0.f;

    int a_r  = (lane & 7) | (((lane >> 3) & 1) << 3);
    int a_cs = lane >> 4;
    int b_r  = (lane & 7) | (((lane >> 4) & 1) << 3);
    int b_cs = (lane >> 3) & 1;
    uint32_t aRow = (uint32_t)(wm * 64 + a_r);
    uint32_t bRow = (uint32_t)(wn * 64 + b_r);

    GEMM_MAINLOOP(MMA16832_F8, acc)

    int mb = m0 + wm * 64;
    int nb = n0 + wn * 64;
    int r0 = lane >> 2, c0 = (lane & 3) * 2;
    float* rsB = rowsum + (size_t)bz * HW_;

    if (emode == 1) {
        uint8_t* Cb = C8 + (size_t)bz * csb;
        #pragma unroll
        for (int mt = 0; mt < 4; mt++) {
            #pragma unroll
            for (int h = 0; h < 2; h++) {
                int m = mb + mt * 16 + r0 + h * 8;
                float rsum = 0.f;
                #pragma unroll
                for (int nt = 0; nt < 8; nt++) {
                    int n = nb + nt * 8 + c0;
                    float v0 = fexp2(acc[mt][nt][2 * h + 0] * alpha);
                    float v1 = fexp2(acc[mt][nt][2 * h + 1] * alpha);
                    rsum += v0 + v1;
                    *reinterpret_cast<uint16_t*>(Cb + (size_t)m * ldc + n) =
                        pack_e4m3(v0, v1);
                }
                rsum += __shfl_xor_sync(0xffffffffu, rsum, 1);
                rsum += __shfl_xor_sync(0xffffffffu, rsum, 2);
                if ((lane & 3) == 0) atomicAdd(&rsB[m], rsum);
            }
        }
    } else {
        __half* Cb = Ch + (size_t)bz * csb;
        #pragma unroll
        for (int mt = 0; mt < 4; mt++) {
            #pragma unroll
            for (int h = 0; h < 2; h++) {
                int m = mb + mt * 16 + r0 + h * 8;
                float inv = 1.0f / rsB[m];
                #pragma unroll
                for (int nt = 0; nt < 8; nt++) {
                    int n = nb + nt * 8 + c0;
                    float v0 = acc[mt][nt][2 * h + 0] * inv;
                    float v1 = acc[mt][nt][2 * h + 1] * inv;
                    *reinterpret_cast<__half2*>(Cb + (size_t)m * ldc + n) =
                        __floats2half2_rn(v0, v1);
                }
            }
        }
    }
}

// ============================ Launcher =====================================
extern "C" void kernel_launch(void* const* d_in, const int* in_sizes, int n_in,
                              void* d_out, int out_size)
{
    const float* q     = (const float*)d_in[0];
    const float* gamma = (const float*)d_in[1];
    const float* beta  = (const float*)d_in[2];
    const float* wq    = (const float*)d_in[3];
    const float* bq    = (const float*)d_in[4];
    const float* wk    = (const float*)d_in[5];
    const float* bk    = (const float*)d_in[6];
    const float* wv    = (const float*)d_in[7];
    const float* bv    = (const float*)d_in[8];
    const float* wo    = (const float*)d_in[9];
    const float* bo    = (const float*)d_in[10];
    float* out = (float*)d_out;

    __half *xt, *ot, *wh;
    uint8_t *qk8, *v8, *st8;
    float *bqk, *rsum;
    cudaGetSymbolAddress((void**)&xt,  g_xt);
    cudaGetSymbolAddress((void**)&qk8, g_qk8);
    cudaGetSymbolAddress((void**)&v8,  g_v8);
    cudaGetSymbolAddress((void**)&st8, g_st8);
    cudaGetSymbolAddress((void**)&ot,  g_ot);
    cudaGetSymbolAddress((void**)&wh,  g_wh);
    cudaGetSymbolAddress((void**)&bqk, g_bqk);
    cudaGetSymbolAddress((void**)&rsum, g_rsum);
    __half* wqh = wh;
    __half* wvh = wh + 2 * (size_t)C_ * C_;
    __half* woh = wh + 3 * (size_t)C_ * C_;

    static int smem_set = 0;
    if (!smem_set) {
        cudaFuncSetAttribute(mm_h, cudaFuncAttributeMaxDynamicSharedMemorySize,
                             SMEM_SZ);
        cudaFuncSetAttribute(mm_h16_o8,
                             cudaFuncAttributeMaxDynamicSharedMemorySize,
                             SMEM_SZ);
        cudaFuncSetAttribute(mm_f8,
                             cudaFuncAttributeMaxDynamicSharedMemorySize,
                             SMEM_SZ);
        smem_set = 1;
    }

    const long CB   = (long)C_ * HW_;         // fp16 per-batch (elements)
    const long QK8B = (long)HW_ * 1024;       // fp8 bytes
    const long V8B  = (long)C_ * HW_;         // fp8 bytes
    const long S8B  = (long)HW_ * HW_;        // fp8 bytes

    int prep_n = 4 * C_ * C_ / 4 + 1024 + B_ * HW_;
    prep_kernel<<<(prep_n + 255) / 256, 256>>>(wq, wk, wv, wo, wh,
                                               bq, bk, bqk, rsum);

    gn_fused<<<B_ * NG_, 256>>>(q, gamma, beta, xt);

    // QK proj (fp16 acc -> fp8 out): M=4096(j), N=1024, K=512
    dim3 gQK(1024 / BN, HW_ / BM, B_);
    mm_h16_o8<<<gQK, 128, SMEM_SZ>>>(xt, C_, CB,  wqh, C_, 0,
                                     qk8, 1024, QK8B,
                                     nullptr, bqk, C_ / 64);

    // V proj (fp16 acc -> fp8 out): M=512(c), N=4096(i), K=512
    dim3 gV(HW_ / BN, C_ / BM, B_);
    mm_h16_o8<<<gV, 128, SMEM_SZ>>>(wvh, C_, 0,  xt, C_, CB,
                                    v8, HW_, V8B,
                                    bv, nullptr, C_ / 64);

    // scores (fp8): P = exp2(alpha * Q@K^T), rowsums. K=512 fp8 -> T=4
    dim3 gS(HW_ / BN, HW_ / BM, B_);
    mm_f8<<<gS, 128, SMEM_SZ>>>(qk8, 1024, QK8B,  qk8 + 512, 1024, QK8B,
                                st8, nullptr, HW_, S8B,
                                0.044194173824159216f * 1.4426950408889634f,
                                512 / 128, rsum, 1);

    // PV (fp8): Ot = (P@V^T)/rowsum. K=4096 fp8 -> T=32
    dim3 gP(C_ / BN, HW_ / BM, B_);
    mm_f8<<<gP, 128, SMEM_SZ>>>(st8, HW_, S8B,  v8, HW_, V8B,
                                nullptr, ot, C_, CB,
                                1.0f, HW_ / 128, rsum, 2);

    // final conv (fp32 acc, residual + fp32 out)
    mm_h<<<gV, 128, SMEM_SZ>>>(woh, C_, 0,  ot, C_, CB,
                               out, HW_, CB,
                               bo, q, CB, 0.7071067811865476f, C_ / 64);
}

// round 13
// speedup vs baseline: 1.1742x; 1.1742x over previous
#include <cuda_runtime.h>
#include <cuda_fp16.h>
#include <cstdint>
#include <math.h>

// ---------------------------------------------------------------------------
// Attention2D (b=4, c=512, hw=4096) — Round 13.
// = R11 (fp16-acc MMA everywhere, fp32-acc final conv, fused softmax)
// + 4-way batch-parallel stream pipelining under graph capture:
//   each batch's QK->V->scores->PV->conv chain runs on its own stream,
//   overlapping wave tails and dependency bubbles across batches.
// ---------------------------------------------------------------------------

#define B_  4
#define C_  512
#define HW_ 4096
#define NG_ 32
#define CPG_ (C_ / NG_)
#define GRP_ELEMS (CPG_ * HW_)

__device__ __align__(256) __half g_xt[(size_t)B_ * HW_ * C_];
__device__ __align__(256) __half g_qk[(size_t)B_ * HW_ * 1024];
__device__ __align__(256) __half g_v [(size_t)B_ * C_ * HW_];
__device__ __align__(256) __half g_st[(size_t)B_ * HW_ * HW_];
__device__ __align__(256) __half g_ot[(size_t)B_ * HW_ * C_];
__device__ __align__(256) __half g_wh[4][(size_t)C_ * C_];
__device__ float  g_bqk[1024];
__device__ float  g_rsum[B_ * HW_];

// ================= weight convert + bias cat + rsum zero ==================
__global__ __launch_bounds__(256) void prep_kernel(
    const float* __restrict__ w0, const float* __restrict__ w1,
    const float* __restrict__ w2, const float* __restrict__ w3,
    __half* __restrict__ o,
    const float* __restrict__ bq, const float* __restrict__ bk,
    float* __restrict__ bqk, float* __restrict__ rs)
{
    const int n4 = C_ * C_ / 4;
    int i = blockIdx.x * blockDim.x + threadIdx.x;
    if (i < 4 * n4) {
        int w = i >> 16;
        int e = i & (n4 - 1);
        const float* src = (w == 0) ? w0 : (w == 1) ? w1 : (w == 2) ? w2 : w3;
        float4 v = reinterpret_cast<const float4*>(src)[e];
        __half2 h0 = __floats2half2_rn(v.x, v.y);
        __half2 h1 = __floats2half2_rn(v.z, v.w);
        __half2* dst = reinterpret_cast<__half2*>(o + (size_t)w * C_ * C_);
        dst[2 * e] = h0;
        dst[2 * e + 1] = h1;
    } else if (i < 4 * n4 + 1024) {
        int ii = i - 4 * n4;
        bqk[ii] = (ii < C_) ? bq[ii] : bk[ii - C_];
    } else {
        int jj = i - 4 * n4 - 1024;
        if (jj < B_ * HW_) rs[jj] = 0.f;
    }
}

// ================= GroupNorm fused: stats + apply + transpose ==============
#define TP 514
__global__ __launch_bounds__(256) void gn_fused(
    const float* __restrict__ x, const float* __restrict__ gamma,
    const float* __restrict__ beta, __half* __restrict__ xt)
{
    __shared__ float T[CPG_][TP];
    __shared__ float rs[8], rss[8];
    __shared__ float sc[CPG_], sh[CPG_];

    int b = blockIdx.x / NG_, g = blockIdx.x % NG_;
    size_t base = ((size_t)b * C_ + (size_t)g * CPG_) * HW_;
    int t = threadIdx.x;

    const float4* x4 = reinterpret_cast<const float4*>(x + base);
    float s = 0.f, ss = 0.f;
    for (int i = t; i < GRP_ELEMS / 4; i += 256) {
        float4 v = x4[i];
        s  += v.x + v.y + v.z + v.w;
        ss += v.x * v.x + v.y * v.y + v.z * v.z + v.w * v.w;
    }
    #pragma unroll
    for (int o = 16; o; o >>= 1) {
        s  += __shfl_xor_sync(0xffffffffu, s,  o);
        ss += __shfl_xor_sync(0xffffffffu, ss, o);
    }
    if ((t & 31) == 0) { rs[t >> 5] = s; rss[t >> 5] = ss; }
    __syncthreads();
    if (t < CPG_) {
        float ts = 0.f, tss = 0.f;
        #pragma unroll
        for (int i = 0; i < 8; i++) { ts += rs[i]; tss += rss[i]; }
        float inv_n = 1.0f / (float)GRP_ELEMS;
        float mu  = ts * inv_n;
        float var = tss * inv_n - mu * mu;
        float rstd = rsqrtf(var + 1e-6f);
        int c = g * CPG_ + t;
        float gm = gamma[c] * rstd;
        sc[t] = gm;
        sh[t] = beta[c] - mu * gm;
    }
    __syncthreads();

    size_t tb = (size_t)b * HW_ * C_ + (size_t)g * CPG_;
    for (int j0 = 0; j0 < HW_; j0 += 512) {
        #pragma unroll
        for (int i = 0; i < 32; i++) {
            int idx = i * 256 + t;
            int c = idx >> 9;
            int j = idx & 511;
            float v = x[base + (size_t)c * HW_ + j0 + j];
            T[c][j] = v * sc[c] + sh[c];
        }
        __syncthreads();
        #pragma unroll
        for (int i = 0; i < 16; i++) {
            int idx = i * 256 + t;
            int j  = idx >> 3;
            int cq = idx & 7;
            __half2 h = __floats2half2_rn(T[2 * cq][j], T[2 * cq + 1][j]);
            *reinterpret_cast<__half2*>(xt + tb + (size_t)(j0 + j) * C_ + 2 * cq) = h;
        }
        __syncthreads();
    }
}

// ========================= common GEMM pieces ==============================
#define BM 128
#define BN 128
#define BK 64
#define NSTAGE 3
#define STAGE_B (2 * BM * BK)
#define SMEM_SZ (NSTAGE * 2 * STAGE_B)   // 96 KB

__device__ __forceinline__ uint32_t smem_u32(const void* p) {
    uint32_t a;
    asm("{ .reg .u64 t; cvta.to.shared.u64 t, %1; cvt.u32.u64 %0, t; }"
        : "=r"(a) : "l"(p));
    return a;
}

__device__ __forceinline__ float fexp2(float x) {
    x = fmaxf(x, -120.f);
    float k = rintf(x);
    float r = x - k;
    float p = 0.0013333558f;
    p = fmaf(p, r, 0.0096181291f);
    p = fmaf(p, r, 0.0555041087f);
    p = fmaf(p, r, 0.2402265069f);
    p = fmaf(p, r, 0.6931471806f);
    p = fmaf(p, r, 1.0f);
    return p * __int_as_float(((int)k + 127) << 23);
}

__device__ __forceinline__ void load_tile_h(
    uint32_t sdst, const __half* __restrict__ src, long ld, int tid)
{
    #pragma unroll
    for (int i = 0; i < 8; i++) {
        int idx = tid + (i << 7);
        int r = idx >> 3;
        int c = idx & 7;
        uint32_t sw = (uint32_t)r * 128 + (uint32_t)((c ^ (r & 7)) << 4);
        asm volatile("cp.async.cg.shared.global [%0], [%1], 16;"
                     :: "r"(sdst + sw), "l"(src + (long)r * ld + (c << 3))
                     : "memory");
    }
}

#define LDSM4(r0, r1, r2, r3, a)                                           \
    asm volatile("ldmatrix.sync.aligned.m8n8.x4.shared.b16 {%0,%1,%2,%3}, [%4];" \
                 : "=r"(r0), "=r"(r1), "=r"(r2), "=r"(r3) : "r"(a))

#define MMA16816(acc, av, b0, b1)                                           \
    asm volatile(                                                           \
        "mma.sync.aligned.m16n8k16.row.col.f32.f16.f16.f32 "                \
        "{%0,%1,%2,%3}, {%4,%5,%6,%7}, {%8,%9}, {%0,%1,%2,%3};"             \
        : "+f"((acc)[0]), "+f"((acc)[1]), "+f"((acc)[2]), "+f"((acc)[3])    \
        : "r"((av)[0]), "r"((av)[1]), "r"((av)[2]), "r"((av)[3]),           \
          "r"(b0), "r"(b1))

#define MMA16816_H(acc, av, b0, b1)                                         \
    asm volatile(                                                           \
        "mma.sync.aligned.m16n8k16.row.col.f16.f16.f16.f16 "                \
        "{%0,%1}, {%2,%3,%4,%5}, {%6,%7}, {%0,%1};"                         \
        : "+r"((acc)[0]), "+r"((acc)[1])                                    \
        : "r"((av)[0]), "r"((av)[1]), "r"((av)[2]), "r"((av)[3]),           \
          "r"(b0), "r"(b1))

// =============== fp32-acc GEMM (final conv: residual + fp32 out) ===========
__global__ __launch_bounds__(128, 2) void mm_h(
    const __half* __restrict__ A, long lda,
    const __half* __restrict__ Bp, long ldb,
    float* __restrict__ Cf, long ldc,
    const float* __restrict__ bias_m,
    const float* __restrict__ res, float alpha, int T)
{
    extern __shared__ __half smem[];
    uint32_t sb = smem_u32(smem);
    uint32_t sA[NSTAGE], sB[NSTAGE];
    #pragma unroll
    for (int s = 0; s < NSTAGE; s++) {
        sA[s] = sb + (uint32_t)s * 2 * STAGE_B;
        sB[s] = sA[s] + STAGE_B;
    }

    int tid = threadIdx.x, lane = tid & 31, wid = tid >> 5;
    int wm = wid >> 1, wn = wid & 1;
    int m0 = blockIdx.y * BM, n0 = blockIdx.x * BN;

    const __half* Ab = A + (size_t)m0 * lda;
    const __half* Bb = Bp + (size_t)n0 * ldb;

    float acc[4][8][4];
    #pragma unroll
    for (int i = 0; i < 4; i++)
        #pragma unroll
        for (int j = 0; j < 8; j++)
            #pragma unroll
            for (int k = 0; k < 4; k++) acc[i][j][k] = 0.f;

    int a_r  = (lane & 7) | (((lane >> 3) & 1) << 3);
    int a_cs = lane >> 4;
    int b_r  = (lane & 7) | (((lane >> 4) & 1) << 3);
    int b_cs = (lane >> 3) & 1;
    uint32_t aRow = (uint32_t)(wm * 64 + a_r);
    uint32_t bRow = (uint32_t)(wn * 64 + b_r);

    load_tile_h(sA[0], Ab, lda, tid);
    load_tile_h(sB[0], Bb, ldb, tid);
    asm volatile("cp.async.commit_group;");
    if (T > 1) {
        load_tile_h(sA[1], Ab + (size_t)BK, lda, tid);
        load_tile_h(sB[1], Bb + (size_t)BK, ldb, tid);
    }
    asm volatile("cp.async.commit_group;");

    for (int t = 0; t < T; t++) {
        int cs = t % NSTAGE;
        asm volatile("cp.async.wait_group 1;");
        __syncthreads();

        if (t + 2 < T) {
            int ns = (t + 2) % NSTAGE;
            load_tile_h(sA[ns], Ab + (size_t)(t + 2) * BK, lda, tid);
            load_tile_h(sB[ns], Bb + (size_t)(t + 2) * BK, ldb, tid);
        }
        asm volatile("cp.async.commit_group;");

        #pragma unroll
        for (int ks = 0; ks < 4; ks++) {
            int ach = ks * 2 + a_cs;
            int bch = ks * 2 + b_cs;

            uint32_t b0[4], b1[4];
            {
                uint32_t row = bRow;
                uint32_t addr = sB[cs] + row * 128
                              + (uint32_t)((bch ^ (row & 7)) << 4);
                LDSM4(b0[0], b0[1], b0[2], b0[3], addr);
            }
            uint32_t a[4][4];
            #pragma unroll
            for (int mt = 0; mt < 4; mt++) {
                uint32_t row = aRow + mt * 16;
                uint32_t addr = sA[cs] + row * 128
                              + (uint32_t)((ach ^ (row & 7)) << 4);
                LDSM4(a[mt][0], a[mt][1], a[mt][2], a[mt][3], addr);
            }

            #pragma unroll
            for (int p = 0; p < 4; p++) {
                uint32_t* bc = (p & 1) ? b1 : b0;
                uint32_t* bn = (p & 1) ? b0 : b1;
                if (p < 3) {
                    uint32_t row = bRow + (p + 1) * 16;
                    uint32_t addr = sB[cs] + row * 128
                                  + (uint32_t)((bch ^ (row & 7)) << 4);
                    LDSM4(bn[0], bn[1], bn[2], bn[3], addr);
                }
                #pragma unroll
                for (int mt = 0; mt < 4; mt++) {
                    MMA16816(acc[mt][2 * p],     a[mt], bc[0], bc[1]);
                    MMA16816(acc[mt][2 * p + 1], a[mt], bc[2], bc[3]);
                }
            }
        }
    }

    int mb = m0 + wm * 64;
    int nb = n0 + wn * 64;
    int r0 = lane >> 2, c0 = (lane & 3) * 2;

    #pragma unroll
    for (int mt = 0; mt < 4; mt++) {
        #pragma unroll
        for (int h = 0; h < 2; h++) {
            int m = mb + mt * 16 + r0 + h * 8;
            float bmv = bias_m[m];
            #pragma unroll
            for (int nt = 0; nt < 8; nt++) {
                int n = nb + nt * 8 + c0;
                const float* rp = res + (size_t)m * ldc + n;
                float v0 = (acc[mt][nt][2 * h + 0] + bmv + rp[0]) * alpha;
                float v1 = (acc[mt][nt][2 * h + 1] + bmv + rp[1]) * alpha;
                *reinterpret_cast<float2*>(Cf + (size_t)m * ldc + n) =
                    make_float2(v0, v1);
            }
        }
    }
}

// ================= fp16-acc GEMM (QK / V / scores / PV) ====================
// emode: 0 = bias_m/bias_n + store fp16
//        1 = alpha, exp2, atomic rowsum, store fp16
//        2 = divide by rowsum, store fp16
__global__ __launch_bounds__(128, 2) void mm_h16(
    const __half* __restrict__ A, long lda,
    const __half* __restrict__ Bp, long ldb,
    __half* __restrict__ Ch, long ldc,
    const float* __restrict__ bias_m, const float* __restrict__ bias_n,
    float alpha, int T, float* __restrict__ rowsum, int emode)
{
    extern __shared__ __half smem[];
    uint32_t sb = smem_u32(smem);
    uint32_t sA[NSTAGE], sB[NSTAGE];
    #pragma unroll
    for (int s = 0; s < NSTAGE; s++) {
        sA[s] = sb + (uint32_t)s * 2 * STAGE_B;
        sB[s] = sA[s] + STAGE_B;
    }

    int tid = threadIdx.x, lane = tid & 31, wid = tid >> 5;
    int wm = wid >> 1, wn = wid & 1;
    int m0 = blockIdx.y * BM, n0 = blockIdx.x * BN;

    const __half* Ab = A + (size_t)m0 * lda;
    const __half* Bb = Bp + (size_t)n0 * ldb;

    uint32_t acc[4][8][2];
    #pragma unroll
    for (int i = 0; i < 4; i++)
        #pragma unroll
        for (int j = 0; j < 8; j++) { acc[i][j][0] = 0u; acc[i][j][1] = 0u; }

    int a_r  = (lane & 7) | (((lane >> 3) & 1) << 3);
    int a_cs = lane >> 4;
    int b_r  = (lane & 7) | (((lane >> 4) & 1) << 3);
    int b_cs = (lane >> 3) & 1;
    uint32_t aRow = (uint32_t)(wm * 64 + a_r);
    uint32_t bRow = (uint32_t)(wn * 64 + b_r);

    load_tile_h(sA[0], Ab, lda, tid);
    load_tile_h(sB[0], Bb, ldb, tid);
    asm volatile("cp.async.commit_group;");
    if (T > 1) {
        load_tile_h(sA[1], Ab + (size_t)BK, lda, tid);
        load_tile_h(sB[1], Bb + (size_t)BK, ldb, tid);
    }
    asm volatile("cp.async.commit_group;");

    for (int t = 0; t < T; t++) {
        int cs = t % NSTAGE;
        asm volatile("cp.async.wait_group 1;");
        __syncthreads();

        if (t + 2 < T) {
            int ns = (t + 2) % NSTAGE;
            load_tile_h(sA[ns], Ab + (size_t)(t + 2) * BK, lda, tid);
            load_tile_h(sB[ns], Bb + (size_t)(t + 2) * BK, ldb, tid);
        }
        asm volatile("cp.async.commit_group;");

        #pragma unroll
        for (int ks = 0; ks < 4; ks++) {
            int ach = ks * 2 + a_cs;
            int bch = ks * 2 + b_cs;

            uint32_t b0[4], b1[4];
            {
                uint32_t row = bRow;
                uint32_t addr = sB[cs] + row * 128
                              + (uint32_t)((bch ^ (row & 7)) << 4);
                LDSM4(b0[0], b0[1], b0[2], b0[3], addr);
            }
            uint32_t a[4][4];
            #pragma unroll
            for (int mt = 0; mt < 4; mt++) {
                uint32_t row = aRow + mt * 16;
                uint32_t addr = sA[cs] + row * 128
                              + (uint32_t)((ach ^ (row & 7)) << 4);
                LDSM4(a[mt][0], a[mt][1], a[mt][2], a[mt][3], addr);
            }

            #pragma unroll
            for (int p = 0; p < 4; p++) {
                uint32_t* bc = (p & 1) ? b1 : b0;
                uint32_t* bn = (p & 1) ? b0 : b1;
                if (p < 3) {
                    uint32_t row = bRow + (p + 1) * 16;
                    uint32_t addr = sB[cs] + row * 128
                                  + (uint32_t)((bch ^ (row & 7)) << 4);
                    LDSM4(bn[0], bn[1], bn[2], bn[3], addr);
                }
                #pragma unroll
                for (int mt = 0; mt < 4; mt++) {
                    MMA16816_H(acc[mt][2 * p],     a[mt], bc[0], bc[1]);
                    MMA16816_H(acc[mt][2 * p + 1], a[mt], bc[2], bc[3]);
                }
            }
        }
    }

    int mb = m0 + wm * 64;
    int nb = n0 + wn * 64;
    int r0 = lane >> 2, c0 = (lane & 3) * 2;

    #pragma unroll
    for (int mt = 0; mt < 4; mt++) {
        #pragma unroll
        for (int h = 0; h < 2; h++) {
            int m = mb + mt * 16 + r0 + h * 8;
            float bmv = bias_m ? bias_m[m] : 0.f;
            float inv = 1.0f;
            if (emode == 2) inv = 1.0f / rowsum[m];
            float rsum = 0.f;
            #pragma unroll
            for (int nt = 0; nt < 8; nt++) {
                int n = nb + nt * 8 + c0;
                float2 f = __half22float2(
                    *reinterpret_cast<__half2*>(&acc[mt][nt][h]));
                float v0 = f.x, v1 = f.y;
                if (emode == 1) {
                    v0 = fexp2(v0 * alpha);
                    v1 = fexp2(v1 * alpha);
                    rsum += v0 + v1;
                } else if (emode == 2) {
                    v0 *= inv; v1 *= inv;
                } else {
                    v0 += bmv; v1 += bmv;
                    if (bias_n) { v0 += bias_n[n]; v1 += bias_n[n + 1]; }
                }
                *reinterpret_cast<__half2*>(Ch + (size_t)m * ldc + n) =
                    __floats2half2_rn(v0, v1);
            }
            if (emode == 1) {
                rsum += __shfl_xor_sync(0xffffffffu, rsum, 1);
                rsum += __shfl_xor_sync(0xffffffffu, rsum, 2);
                if ((lane & 3) == 0) atomicAdd(&rowsum[m], rsum);
            }
        }
    }
}

// ============================ Launcher =====================================
extern "C" void kernel_launch(void* const* d_in, const int* in_sizes, int n_in,
                              void* d_out, int out_size)
{
    const float* q     = (const float*)d_in[0];
    const float* gamma = (const float*)d_in[1];
    const float* beta  = (const float*)d_in[2];
    const float* wq    = (const float*)d_in[3];
    const float* bq    = (const float*)d_in[4];
    const float* wk    = (const float*)d_in[5];
    const float* bk    = (const float*)d_in[6];
    const float* wv    = (const float*)d_in[7];
    const float* bv    = (const float*)d_in[8];
    const float* wo    = (const float*)d_in[9];
    const float* bo    = (const float*)d_in[10];
    float* out = (float*)d_out;

    __half *xt, *qk, *v, *st, *ot, *wh;
    float *bqk, *rsum;
    cudaGetSymbolAddress((void**)&xt, g_xt);
    cudaGetSymbolAddress((void**)&qk, g_qk);
    cudaGetSymbolAddress((void**)&v,  g_v);
    cudaGetSymbolAddress((void**)&st, g_st);
    cudaGetSymbolAddress((void**)&ot, g_ot);
    cudaGetSymbolAddress((void**)&wh, g_wh);
    cudaGetSymbolAddress((void**)&bqk, g_bqk);
    cudaGetSymbolAddress((void**)&rsum, g_rsum);
    __half* wqh = wh;
    __half* wvh = wh + 2 * (size_t)C_ * C_;
    __half* woh = wh + 3 * (size_t)C_ * C_;

    // one-time setup (first call is the non-captured correctness run)
    static int inited = 0;
    static cudaStream_t sx[B_ - 1];
    static cudaEvent_t  efork, ejoin[B_ - 1];
    if (!inited) {
        cudaFuncSetAttribute(mm_h, cudaFuncAttributeMaxDynamicSharedMemorySize,
                             SMEM_SZ);
        cudaFuncSetAttribute(mm_h16,
                             cudaFuncAttributeMaxDynamicSharedMemorySize,
                             SMEM_SZ);
        for (int i = 0; i < B_ - 1; i++)
            cudaStreamCreateWithFlags(&sx[i], cudaStreamNonBlocking);
        cudaEventCreateWithFlags(&efork, cudaEventDisableTiming);
        for (int i = 0; i < B_ - 1; i++)
            cudaEventCreateWithFlags(&ejoin[i], cudaEventDisableTiming);
        inited = 1;
    }

    const size_t CB  = (size_t)C_ * HW_;
    const size_t QKB = (size_t)HW_ * 1024;
    const size_t SB  = (size_t)HW_ * HW_;
    const float SCALE2 = 0.044194173824159216f * 1.4426950408889634f;

    // ---- stream 0: prep + groupnorm (all batches) ----
    int prep_n = 4 * C_ * C_ / 4 + 1024 + B_ * HW_;
    prep_kernel<<<(prep_n + 255) / 256, 256>>>(wq, wk, wv, wo, wh,
                                               bq, bk, bqk, rsum);
    gn_fused<<<B_ * NG_, 256>>>(q, gamma, beta, xt);

    // ---- fork ----
    cudaEventRecord(efork, 0);
    for (int i = 0; i < B_ - 1; i++) cudaStreamWaitEvent(sx[i], efork, 0);

    dim3 gQK(1024 / BN, HW_ / BM);   // (8, 32)
    dim3 gV(HW_ / BN, C_ / BM);      // (32, 4)
    dim3 gS(HW_ / BN, HW_ / BM);     // (32, 32)
    dim3 gP(C_ / BN, HW_ / BM);      // (4, 32)

    for (int b = 0; b < B_; b++) {
        cudaStream_t s = (b == 0) ? (cudaStream_t)0 : sx[b - 1];
        const __half* xtb = xt + (size_t)b * CB;
        __half* qkb = qk + (size_t)b * QKB;
        __half* vb  = v  + (size_t)b * CB;
        __half* stb = st + (size_t)b * SB;
        __half* otb = ot + (size_t)b * CB;
        float*  rsb = rsum + (size_t)b * HW_;
        const float* qb = q + (size_t)b * CB;
        float* outb = out + (size_t)b * CB;

        // QK proj: M=4096(j), N=1024(q|k), K=512
        mm_h16<<<gQK, 128, SMEM_SZ, s>>>(xtb, C_,  wqh, C_,
                                         qkb, 1024,
                                         nullptr, bqk, 1.0f, C_ / BK,
                                         nullptr, 0);
        // V proj: M=512(c), N=4096(i), K=512
        mm_h16<<<gV, 128, SMEM_SZ, s>>>(wvh, C_,  xtb, C_,
                                        vb, HW_,
                                        bv, nullptr, 1.0f, C_ / BK,
                                        nullptr, 0);
        // scores: P = exp2(alpha * Q@K^T) + rowsums
        mm_h16<<<gS, 128, SMEM_SZ, s>>>(qkb, 1024,  qkb + 512, 1024,
                                        stb, HW_,
                                        nullptr, nullptr, SCALE2, C_ / BK,
                                        rsb, 1);
        // PV: Ot = (P@V^T)/rowsum
        mm_h16<<<gP, 128, SMEM_SZ, s>>>(stb, HW_,  vb, HW_,
                                        otb, C_,
                                        nullptr, nullptr, 1.0f, HW_ / BK,
                                        rsb, 2);
        // final conv: out = (Wo@Ot^T + bo + q) * inv_sqrt2
        mm_h<<<gV, 128, SMEM_SZ, s>>>(woh, C_,  otb, C_,
                                      outb, HW_,
                                      bo, qb, 0.7071067811865476f, C_ / BK);
    }

    // ---- join ----
    for (int i = 0; i < B_ - 1; i++) {
        cudaEventRecord(ejoin[i], sx[i]);
        cudaStreamWaitEvent(0, ejoin[i], 0);
    }
}

// round 15
// speedup vs baseline: 1.2159x; 1.0356x over previous
#include <cuda_runtime.h>
#include <cuda_fp16.h>
#include <cstdint>
#include <math.h>

// ---------------------------------------------------------------------------
// Attention2D (b=4, c=512, hw=4096) — Round 15.
// = R14 intent (2-stage cp.async ring 64KB + 3 CTAs/SM for fp16 GEMM,
//   prep overlapped with GroupNorm) with the graph-capture fork bug fixed:
//   side streams are forked from the captured origin stream BEFORE any
//   launch lands on them.
// ---------------------------------------------------------------------------

#define B_  4
#define C_  512
#define HW_ 4096
#define NG_ 32
#define CPG_ (C_ / NG_)
#define GRP_ELEMS (CPG_ * HW_)

__device__ __align__(256) __half g_xt[(size_t)B_ * HW_ * C_];
__device__ __align__(256) __half g_qk[(size_t)B_ * HW_ * 1024];
__device__ __align__(256) __half g_v [(size_t)B_ * C_ * HW_];
__device__ __align__(256) __half g_st[(size_t)B_ * HW_ * HW_];
__device__ __align__(256) __half g_ot[(size_t)B_ * HW_ * C_];
__device__ __align__(256) __half g_wh[4][(size_t)C_ * C_];
__device__ float  g_bqk[1024];
__device__ float  g_rsum[B_ * HW_];

// ================= weight convert + bias cat + rsum zero ==================
__global__ __launch_bounds__(256) void prep_kernel(
    const float* __restrict__ w0, const float* __restrict__ w1,
    const float* __restrict__ w2, const float* __restrict__ w3,
    __half* __restrict__ o,
    const float* __restrict__ bq, const float* __restrict__ bk,
    float* __restrict__ bqk, float* __restrict__ rs)
{
    const int n4 = C_ * C_ / 4;
    int i = blockIdx.x * blockDim.x + threadIdx.x;
    if (i < 4 * n4) {
        int w = i >> 16;
        int e = i & (n4 - 1);
        const float* src = (w == 0) ? w0 : (w == 1) ? w1 : (w == 2) ? w2 : w3;
        float4 v = reinterpret_cast<const float4*>(src)[e];
        __half2 h0 = __floats2half2_rn(v.x, v.y);
        __half2 h1 = __floats2half2_rn(v.z, v.w);
        __half2* dst = reinterpret_cast<__half2*>(o + (size_t)w * C_ * C_);
        dst[2 * e] = h0;
        dst[2 * e + 1] = h1;
    } else if (i < 4 * n4 + 1024) {
        int ii = i - 4 * n4;
        bqk[ii] = (ii < C_) ? bq[ii] : bk[ii - C_];
    } else {
        int jj = i - 4 * n4 - 1024;
        if (jj < B_ * HW_) rs[jj] = 0.f;
    }
}

// ================= GroupNorm fused: stats + apply + transpose ==============
#define TP 514
__global__ __launch_bounds__(256) void gn_fused(
    const float* __restrict__ x, const float* __restrict__ gamma,
    const float* __restrict__ beta, __half* __restrict__ xt)
{
    __shared__ float T[CPG_][TP];
    __shared__ float rs[8], rss[8];
    __shared__ float sc[CPG_], sh[CPG_];

    int b = blockIdx.x / NG_, g = blockIdx.x % NG_;
    size_t base = ((size_t)b * C_ + (size_t)g * CPG_) * HW_;
    int t = threadIdx.x;

    const float4* x4 = reinterpret_cast<const float4*>(x + base);
    float s = 0.f, ss = 0.f;
    for (int i = t; i < GRP_ELEMS / 4; i += 256) {
        float4 v = x4[i];
        s  += v.x + v.y + v.z + v.w;
        ss += v.x * v.x + v.y * v.y + v.z * v.z + v.w * v.w;
    }
    #pragma unroll
    for (int o = 16; o; o >>= 1) {
        s  += __shfl_xor_sync(0xffffffffu, s,  o);
        ss += __shfl_xor_sync(0xffffffffu, ss, o);
    }
    if ((t & 31) == 0) { rs[t >> 5] = s; rss[t >> 5] = ss; }
    __syncthreads();
    if (t < CPG_) {
        float ts = 0.f, tss = 0.f;
        #pragma unroll
        for (int i = 0; i < 8; i++) { ts += rs[i]; tss += rss[i]; }
        float inv_n = 1.0f / (float)GRP_ELEMS;
        float mu  = ts * inv_n;
        float var = tss * inv_n - mu * mu;
        float rstd = rsqrtf(var + 1e-6f);
        int c = g * CPG_ + t;
        float gm = gamma[c] * rstd;
        sc[t] = gm;
        sh[t] = beta[c] - mu * gm;
    }
    __syncthreads();

    size_t tb = (size_t)b * HW_ * C_ + (size_t)g * CPG_;
    for (int j0 = 0; j0 < HW_; j0 += 512) {
        #pragma unroll
        for (int i = 0; i < 32; i++) {
            int idx = i * 256 + t;
            int c = idx >> 9;
            int j = idx & 511;
            float v = x[base + (size_t)c * HW_ + j0 + j];
            T[c][j] = v * sc[c] + sh[c];
        }
        __syncthreads();
        #pragma unroll
        for (int i = 0; i < 16; i++) {
            int idx = i * 256 + t;
            int j  = idx >> 3;
            int cq = idx & 7;
            __half2 h = __floats2half2_rn(T[2 * cq][j], T[2 * cq + 1][j]);
            *reinterpret_cast<__half2*>(xt + tb + (size_t)(j0 + j) * C_ + 2 * cq) = h;
        }
        __syncthreads();
    }
}

// ========================= common GEMM pieces ==============================
#define BM 128
#define BN 128
#define BK 64
#define STAGE_B (2 * BM * BK)           // 16 KB per tensor per stage
#define SMEM_SZ (2 * 2 * STAGE_B)       // 2 stages x (A+B) = 64 KB

__device__ __forceinline__ uint32_t smem_u32(const void* p) {
    uint32_t a;
    asm("{ .reg .u64 t; cvta.to.shared.u64 t, %1; cvt.u32.u64 %0, t; }"
        : "=r"(a) : "l"(p));
    return a;
}

__device__ __forceinline__ float fexp2(float x) {
    x = fmaxf(x, -120.f);
    float k = rintf(x);
    float r = x - k;
    float p = 0.0013333558f;
    p = fmaf(p, r, 0.0096181291f);
    p = fmaf(p, r, 0.0555041087f);
    p = fmaf(p, r, 0.2402265069f);
    p = fmaf(p, r, 0.6931471806f);
    p = fmaf(p, r, 1.0f);
    return p * __int_as_float(((int)k + 127) << 23);
}

__device__ __forceinline__ void load_tile_h(
    uint32_t sdst, const __half* __restrict__ src, long ld, int tid)
{
    #pragma unroll
    for (int i = 0; i < 8; i++) {
        int idx = tid + (i << 7);
        int r = idx >> 3;
        int c = idx & 7;
        uint32_t sw = (uint32_t)r * 128 + (uint32_t)((c ^ (r & 7)) << 4);
        asm volatile("cp.async.cg.shared.global [%0], [%1], 16;"
                     :: "r"(sdst + sw), "l"(src + (long)r * ld + (c << 3))
                     : "memory");
    }
}

#define LDSM4(r0, r1, r2, r3, a)                                           \
    asm volatile("ldmatrix.sync.aligned.m8n8.x4.shared.b16 {%0,%1,%2,%3}, [%4];" \
                 : "=r"(r0), "=r"(r1), "=r"(r2), "=r"(r3) : "r"(a))

#define MMA16816(acc, av, b0, b1)                                           \
    asm volatile(                                                           \
        "mma.sync.aligned.m16n8k16.row.col.f32.f16.f16.f32 "                \
        "{%0,%1,%2,%3}, {%4,%5,%6,%7}, {%8,%9}, {%0,%1,%2,%3};"             \
        : "+f"((acc)[0]), "+f"((acc)[1]), "+f"((acc)[2]), "+f"((acc)[3])    \
        : "r"((av)[0]), "r"((av)[1]), "r"((av)[2]), "r"((av)[3]),           \
          "r"(b0), "r"(b1))

#define MMA16816_H(acc, av, b0, b1)                                         \
    asm volatile(                                                           \
        "mma.sync.aligned.m16n8k16.row.col.f16.f16.f16.f16 "                \
        "{%0,%1}, {%2,%3,%4,%5}, {%6,%7}, {%0,%1};"                         \
        : "+r"((acc)[0]), "+r"((acc)[1])                                    \
        : "r"((av)[0]), "r"((av)[1]), "r"((av)[2]), "r"((av)[3]),           \
          "r"(b0), "r"(b1))

// 2-stage mainloop: load t+1 while computing t
#define GEMM_MAINLOOP2(MMA_OP, ACC)                                         \
    load_tile_h(sA[0], Ab, lda, tid);                                       \
    load_tile_h(sB[0], Bb, ldb, tid);                                       \
    asm volatile("cp.async.commit_group;");                                 \
    for (int t = 0; t < T; t++) {                                           \
        int cs = t & 1;                                                     \
        if (t + 1 < T) {                                                    \
            load_tile_h(sA[cs ^ 1], Ab + (size_t)(t + 1) * BK, lda, tid);   \
            load_tile_h(sB[cs ^ 1], Bb + (size_t)(t + 1) * BK, ldb, tid);   \
            asm volatile("cp.async.commit_group;");                         \
            asm volatile("cp.async.wait_group 1;");                         \
        } else {                                                            \
            asm volatile("cp.async.wait_group 0;");                         \
        }                                                                   \
        __syncthreads();                                                    \
        _Pragma("unroll")                                                   \
        for (int ks = 0; ks < 4; ks++) {                                    \
            int ach = ks * 2 + a_cs;                                        \
            int bch = ks * 2 + b_cs;                                        \
            uint32_t b0[4], b1[4];                                          \
            {                                                               \
                uint32_t row = bRow;                                        \
                uint32_t addr = sB[cs] + row * 128                          \
                              + (uint32_t)((bch ^ (row & 7)) << 4);         \
                LDSM4(b0[0], b0[1], b0[2], b0[3], addr);                    \
            }                                                               \
            uint32_t a[4][4];                                               \
            _Pragma("unroll")                                               \
            for (int mt = 0; mt < 4; mt++) {                                \
                uint32_t row = aRow + mt * 16;                              \
                uint32_t addr = sA[cs] + row * 128                          \
                              + (uint32_t)((ach ^ (row & 7)) << 4);         \
                LDSM4(a[mt][0], a[mt][1], a[mt][2], a[mt][3], addr);        \
            }                                                               \
            _Pragma("unroll")                                               \
            for (int p = 0; p < 4; p++) {                                   \
                uint32_t* bc = (p & 1) ? b1 : b0;                           \
                uint32_t* bn = (p & 1) ? b0 : b1;                           \
                if (p < 3) {                                                \
                    uint32_t row = bRow + (p + 1) * 16;                     \
                    uint32_t addr = sB[cs] + row * 128                      \
                                  + (uint32_t)((bch ^ (row & 7)) << 4);     \
                    LDSM4(bn[0], bn[1], bn[2], bn[3], addr);                \
                }                                                           \
                _Pragma("unroll")                                           \
                for (int mt = 0; mt < 4; mt++) {                            \
                    MMA_OP(ACC[mt][2 * p],     a[mt], bc[0], bc[1]);        \
                    MMA_OP(ACC[mt][2 * p + 1], a[mt], bc[2], bc[3]);        \
                }                                                           \
            }                                                               \
        }                                                                   \
        __syncthreads();                                                    \
    }

// =============== fp32-acc GEMM (final conv: residual + fp32 out) ===========
__global__ __launch_bounds__(128, 2) void mm_h(
    const __half* __restrict__ A, long lda,
    const __half* __restrict__ Bp, long ldb,
    float* __restrict__ Cf, long ldc,
    const float* __restrict__ bias_m,
    const float* __restrict__ res, float alpha, int T)
{
    extern __shared__ __half smem[];
    uint32_t sb = smem_u32(smem);
    uint32_t sA[2], sB[2];
    #pragma unroll
    for (int s = 0; s < 2; s++) {
        sA[s] = sb + (uint32_t)s * 2 * STAGE_B;
        sB[s] = sA[s] + STAGE_B;
    }

    int tid = threadIdx.x, lane = tid & 31, wid = tid >> 5;
    int wm = wid >> 1, wn = wid & 1;
    int m0 = blockIdx.y * BM, n0 = blockIdx.x * BN;

    const __half* Ab = A + (size_t)m0 * lda;
    const __half* Bb = Bp + (size_t)n0 * ldb;

    float acc[4][8][4];
    #pragma unroll
    for (int i = 0; i < 4; i++)
        #pragma unroll
        for (int j = 0; j < 8; j++)
            #pragma unroll
            for (int k = 0; k < 4; k++) acc[i][j][k] = 0.f;

    int a_r  = (lane & 7) | (((lane >> 3) & 1) << 3);
    int a_cs = lane >> 4;
    int b_r  = (lane & 7) | (((lane >> 4) & 1) << 3);
    int b_cs = (lane >> 3) & 1;
    uint32_t aRow = (uint32_t)(wm * 64 + a_r);
    uint32_t bRow = (uint32_t)(wn * 64 + b_r);

    GEMM_MAINLOOP2(MMA16816, acc)

    int mb = m0 + wm * 64;
    int nb = n0 + wn * 64;
    int r0 = lane >> 2, c0 = (lane & 3) * 2;

    #pragma unroll
    for (int mt = 0; mt < 4; mt++) {
        #pragma unroll
        for (int h = 0; h < 2; h++) {
            int m = mb + mt * 16 + r0 + h * 8;
            float bmv = bias_m[m];
            #pragma unroll
            for (int nt = 0; nt < 8; nt++) {
                int n = nb + nt * 8 + c0;
                const float* rp = res + (size_t)m * ldc + n;
                float v0 = (acc[mt][nt][2 * h + 0] + bmv + rp[0]) * alpha;
                float v1 = (acc[mt][nt][2 * h + 1] + bmv + rp[1]) * alpha;
                *reinterpret_cast<float2*>(Cf + (size_t)m * ldc + n) =
                    make_float2(v0, v1);
            }
        }
    }
}

// ================= fp16-acc GEMM (QK / V / scores / PV) ====================
// emode: 0 = bias, 1 = exp2 + atomic rowsum, 2 = divide by rowsum
__global__ __launch_bounds__(128, 3) void mm_h16(
    const __half* __restrict__ A, long lda,
    const __half* __restrict__ Bp, long ldb,
    __half* __restrict__ Ch, long ldc,
    const float* __restrict__ bias_m, const float* __restrict__ bias_n,
    float alpha, int T, float* __restrict__ rowsum, int emode)
{
    extern __shared__ __half smem[];
    uint32_t sb = smem_u32(smem);
    uint32_t sA[2], sB[2];
    #pragma unroll
    for (int s = 0; s < 2; s++) {
        sA[s] = sb + (uint32_t)s * 2 * STAGE_B;
        sB[s] = sA[s] + STAGE_B;
    }

    int tid = threadIdx.x, lane = tid & 31, wid = tid >> 5;
    int wm = wid >> 1, wn = wid & 1;
    int m0 = blockIdx.y * BM, n0 = blockIdx.x * BN;

    const __half* Ab = A + (size_t)m0 * lda;
    const __half* Bb = Bp + (size_t)n0 * ldb;

    uint32_t acc[4][8][2];
    #pragma unroll
    for (int i = 0; i < 4; i++)
        #pragma unroll
        for (int j = 0; j < 8; j++) { acc[i][j][0] = 0u; acc[i][j][1] = 0u; }

    int a_r  = (lane & 7) | (((lane >> 3) & 1) << 3);
    int a_cs = lane >> 4;
    int b_r  = (lane & 7) | (((lane >> 4) & 1) << 3);
    int b_cs = (lane >> 3) & 1;
    uint32_t aRow = (uint32_t)(wm * 64 + a_r);
    uint32_t bRow = (uint32_t)(wn * 64 + b_r);

    GEMM_MAINLOOP2(MMA16816_H, acc)

    int mb = m0 + wm * 64;
    int nb = n0 + wn * 64;
    int r0 = lane >> 2, c0 = (lane & 3) * 2;

    #pragma unroll
    for (int mt = 0; mt < 4; mt++) {
        #pragma unroll
        for (int h = 0; h < 2; h++) {
            int m = mb + mt * 16 + r0 + h * 8;
            float bmv = bias_m ? bias_m[m] : 0.f;
            float inv = 1.0f;
            if (emode == 2) inv = 1.0f / rowsum[m];
            float rsum = 0.f;
            #pragma unroll
            for (int nt = 0; nt < 8; nt++) {
                int n = nb + nt * 8 + c0;
                float2 f = __half22float2(
                    *reinterpret_cast<__half2*>(&acc[mt][nt][h]));
                float v0 = f.x, v1 = f.y;
                if (emode == 1) {
                    v0 = fexp2(v0 * alpha);
                    v1 = fexp2(v1 * alpha);
                    rsum += v0 + v1;
                } else if (emode == 2) {
                    v0 *= inv; v1 *= inv;
                } else {
                    v0 += bmv; v1 += bmv;
                    if (bias_n) { v0 += bias_n[n]; v1 += bias_n[n + 1]; }
                }
                *reinterpret_cast<__half2*>(Ch + (size_t)m * ldc + n) =
                    __floats2half2_rn(v0, v1);
            }
            if (emode == 1) {
                rsum += __shfl_xor_sync(0xffffffffu, rsum, 1);
                rsum += __shfl_xor_sync(0xffffffffu, rsum, 2);
                if ((lane & 3) == 0) atomicAdd(&rowsum[m], rsum);
            }
        }
    }
}

// ============================ Launcher =====================================
extern "C" void kernel_launch(void* const* d_in, const int* in_sizes, int n_in,
                              void* d_out, int out_size)
{
    const float* q     = (const float*)d_in[0];
    const float* gamma = (const float*)d_in[1];
    const float* beta  = (const float*)d_in[2];
    const float* wq    = (const float*)d_in[3];
    const float* bq    = (const float*)d_in[4];
    const float* wk    = (const float*)d_in[5];
    const float* bk    = (const float*)d_in[6];
    const float* wv    = (const float*)d_in[7];
    const float* bv    = (const float*)d_in[8];
    const float* wo    = (const float*)d_in[9];
    const float* bo    = (const float*)d_in[10];
    float* out = (float*)d_out;

    __half *xt, *qk, *v, *st, *ot, *wh;
    float *bqk, *rsum;
    cudaGetSymbolAddress((void**)&xt, g_xt);
    cudaGetSymbolAddress((void**)&qk, g_qk);
    cudaGetSymbolAddress((void**)&v,  g_v);
    cudaGetSymbolAddress((void**)&st, g_st);
    cudaGetSymbolAddress((void**)&ot, g_ot);
    cudaGetSymbolAddress((void**)&wh, g_wh);
    cudaGetSymbolAddress((void**)&bqk, g_bqk);
    cudaGetSymbolAddress((void**)&rsum, g_rsum);
    __half* wqh = wh;
    __half* wvh = wh + 2 * (size_t)C_ * C_;
    __half* woh = wh + 3 * (size_t)C_ * C_;

    static int inited = 0;
    static cudaStream_t sx[B_ - 1];
    static cudaEvent_t  efork0, eprep, efork, ejoin[B_ - 1];
    if (!inited) {
        cudaFuncSetAttribute(mm_h, cudaFuncAttributeMaxDynamicSharedMemorySize,
                             SMEM_SZ);
        cudaFuncSetAttribute(mm_h16,
                             cudaFuncAttributeMaxDynamicSharedMemorySize,
                             SMEM_SZ);
        for (int i = 0; i < B_ - 1; i++)
            cudaStreamCreateWithFlags(&sx[i], cudaStreamNonBlocking);
        cudaEventCreateWithFlags(&efork0, cudaEventDisableTiming);
        cudaEventCreateWithFlags(&eprep, cudaEventDisableTiming);
        cudaEventCreateWithFlags(&efork, cudaEventDisableTiming);
        for (int i = 0; i < B_ - 1; i++)
            cudaEventCreateWithFlags(&ejoin[i], cudaEventDisableTiming);
        inited = 1;
    }

    const size_t CB  = (size_t)C_ * HW_;
    const size_t QKB = (size_t)HW_ * 1024;
    const size_t SB  = (size_t)HW_ * HW_;
    const float SCALE2 = 0.044194173824159216f * 1.4426950408889634f;

    // ---- legal fork of sx[0] from the captured origin stream FIRST ----
    cudaEventRecord(efork0, 0);
    cudaStreamWaitEvent(sx[0], efork0, 0);

    // prep on sx[0] overlapped with groupnorm on stream 0
    int prep_n = 4 * C_ * C_ / 4 + 1024 + B_ * HW_;
    prep_kernel<<<(prep_n + 255) / 256, 256, 0, sx[0]>>>(wq, wk, wv, wo, wh,
                                                         bq, bk, bqk, rsum);
    cudaEventRecord(eprep, sx[0]);
    gn_fused<<<B_ * NG_, 256>>>(q, gamma, beta, xt);
    cudaStreamWaitEvent(0, eprep, 0);

    // ---- fork for batch streams ----
    cudaEventRecord(efork, 0);
    for (int i = 0; i < B_ - 1; i++) cudaStreamWaitEvent(sx[i], efork, 0);

    dim3 gQK(1024 / BN, HW_ / BM);   // (8, 32)
    dim3 gV(HW_ / BN, C_ / BM);      // (32, 4)
    dim3 gS(HW_ / BN, HW_ / BM);     // (32, 32)
    dim3 gP(C_ / BN, HW_ / BM);      // (4, 32)

    for (int b = 0; b < B_; b++) {
        cudaStream_t s = (b == 0) ? (cudaStream_t)0 : sx[b - 1];
        const __half* xtb = xt + (size_t)b * CB;
        __half* qkb = qk + (size_t)b * QKB;
        __half* vb  = v  + (size_t)b * CB;
        __half* stb = st + (size_t)b * SB;
        __half* otb = ot + (size_t)b * CB;
        float*  rsb = rsum + (size_t)b * HW_;
        const float* qb = q + (size_t)b * CB;
        float* outb = out + (size_t)b * CB;

        mm_h16<<<gQK, 128, SMEM_SZ, s>>>(xtb, C_,  wqh, C_,
                                         qkb, 1024,
                                         nullptr, bqk, 1.0f, C_ / BK,
                                         nullptr, 0);
        mm_h16<<<gV, 128, SMEM_SZ, s>>>(wvh, C_,  xtb, C_,
                                        vb, HW_,
                                        bv, nullptr, 1.0f, C_ / BK,
                                        nullptr, 0);
        mm_h16<<<gS, 128, SMEM_SZ, s>>>(qkb, 1024,  qkb + 512, 1024,
                                        stb, HW_,
                                        nullptr, nullptr, SCALE2, C_ / BK,
                                        rsb, 1);
        mm_h16<<<gP, 128, SMEM_SZ, s>>>(stb, HW_,  vb, HW_,
                                        otb, C_,
                                        nullptr, nullptr, 1.0f, HW_ / BK,
                                        rsb, 2);
        mm_h<<<gV, 128, SMEM_SZ, s>>>(woh, C_,  otb, C_,
                                      outb, HW_,
                                      bo, qb, 0.7071067811865476f, C_ / BK);
    }

    // ---- join ----
    for (int i = 0; i < B_ - 1; i++) {
        cudaEventRecord(ejoin[i], sx[i]);
        cudaStreamWaitEvent(0, ejoin[i], 0);
    }
}

// round 16
// speedup vs baseline: 1.2197x; 1.0031x over previous
#include <cuda_runtime.h>
#include <cuda_fp16.h>
#include <cstdint>
#include <math.h>

// ---------------------------------------------------------------------------
// Attention2D (b=4, c=512, hw=4096) — Round 16.
// = R15 (fp16-acc GEMMs @3 CTAs/SM, 2-stage ring, fused softmax, 4 streams)
// + per-batch GroupNorm on each batch's stream (shrinks the serial head)
// + final conv converted to fp16-acc (residual epilogue) @3 CTAs/SM.
// ---------------------------------------------------------------------------

#define B_  4
#define C_  512
#define HW_ 4096
#define NG_ 32
#define CPG_ (C_ / NG_)
#define GRP_ELEMS (CPG_ * HW_)

__device__ __align__(256) __half g_xt[(size_t)B_ * HW_ * C_];
__device__ __align__(256) __half g_qk[(size_t)B_ * HW_ * 1024];
__device__ __align__(256) __half g_v [(size_t)B_ * C_ * HW_];
__device__ __align__(256) __half g_st[(size_t)B_ * HW_ * HW_];
__device__ __align__(256) __half g_ot[(size_t)B_ * HW_ * C_];
__device__ __align__(256) __half g_wh[4][(size_t)C_ * C_];
__device__ float  g_bqk[1024];
__device__ float  g_rsum[B_ * HW_];

// ================= weight convert + bias cat + rsum zero ==================
__global__ __launch_bounds__(256) void prep_kernel(
    const float* __restrict__ w0, const float* __restrict__ w1,
    const float* __restrict__ w2, const float* __restrict__ w3,
    __half* __restrict__ o,
    const float* __restrict__ bq, const float* __restrict__ bk,
    float* __restrict__ bqk, float* __restrict__ rs)
{
    const int n4 = C_ * C_ / 4;
    int i = blockIdx.x * blockDim.x + threadIdx.x;
    if (i < 4 * n4) {
        int w = i >> 16;
        int e = i & (n4 - 1);
        const float* src = (w == 0) ? w0 : (w == 1) ? w1 : (w == 2) ? w2 : w3;
        float4 v = reinterpret_cast<const float4*>(src)[e];
        __half2 h0 = __floats2half2_rn(v.x, v.y);
        __half2 h1 = __floats2half2_rn(v.z, v.w);
        __half2* dst = reinterpret_cast<__half2*>(o + (size_t)w * C_ * C_);
        dst[2 * e] = h0;
        dst[2 * e + 1] = h1;
    } else if (i < 4 * n4 + 1024) {
        int ii = i - 4 * n4;
        bqk[ii] = (ii < C_) ? bq[ii] : bk[ii - C_];
    } else {
        int jj = i - 4 * n4 - 1024;
        if (jj < B_ * HW_) rs[jj] = 0.f;
    }
}

// ======== GroupNorm fused (per batch): stats + apply + transpose ===========
// grid = NG_ blocks; x/xt are pre-offset to the batch.
#define TP 514
__global__ __launch_bounds__(256) void gn_fused_b(
    const float* __restrict__ x, const float* __restrict__ gamma,
    const float* __restrict__ beta, __half* __restrict__ xt)
{
    __shared__ float T[CPG_][TP];
    __shared__ float rs[8], rss[8];
    __shared__ float sc[CPG_], sh[CPG_];

    int g = blockIdx.x;
    size_t base = (size_t)g * CPG_ * HW_;
    int t = threadIdx.x;

    const float4* x4 = reinterpret_cast<const float4*>(x + base);
    float s = 0.f, ss = 0.f;
    for (int i = t; i < GRP_ELEMS / 4; i += 256) {
        float4 v = x4[i];
        s  += v.x + v.y + v.z + v.w;
        ss += v.x * v.x + v.y * v.y + v.z * v.z + v.w * v.w;
    }
    #pragma unroll
    for (int o = 16; o; o >>= 1) {
        s  += __shfl_xor_sync(0xffffffffu, s,  o);
        ss += __shfl_xor_sync(0xffffffffu, ss, o);
    }
    if ((t & 31) == 0) { rs[t >> 5] = s; rss[t >> 5] = ss; }
    __syncthreads();
    if (t < CPG_) {
        float ts = 0.f, tss = 0.f;
        #pragma unroll
        for (int i = 0; i < 8; i++) { ts += rs[i]; tss += rss[i]; }
        float inv_n = 1.0f / (float)GRP_ELEMS;
        float mu  = ts * inv_n;
        float var = tss * inv_n - mu * mu;
        float rstd = rsqrtf(var + 1e-6f);
        int c = g * CPG_ + t;
        float gm = gamma[c] * rstd;
        sc[t] = gm;
        sh[t] = beta[c] - mu * gm;
    }
    __syncthreads();

    size_t tb = (size_t)g * CPG_;
    for (int j0 = 0; j0 < HW_; j0 += 512) {
        #pragma unroll
        for (int i = 0; i < 32; i++) {
            int idx = i * 256 + t;
            int c = idx >> 9;
            int j = idx & 511;
            float v = x[base + (size_t)c * HW_ + j0 + j];
            T[c][j] = v * sc[c] + sh[c];
        }
        __syncthreads();
        #pragma unroll
        for (int i = 0; i < 16; i++) {
            int idx = i * 256 + t;
            int j  = idx >> 3;
            int cq = idx & 7;
            __half2 h = __floats2half2_rn(T[2 * cq][j], T[2 * cq + 1][j]);
            *reinterpret_cast<__half2*>(xt + tb + (size_t)(j0 + j) * C_ + 2 * cq) = h;
        }
        __syncthreads();
    }
}

// ========================= common GEMM pieces ==============================
#define BM 128
#define BN 128
#define BK 64
#define STAGE_B (2 * BM * BK)           // 16 KB per tensor per stage
#define SMEM_SZ (2 * 2 * STAGE_B)       // 64 KB

__device__ __forceinline__ uint32_t smem_u32(const void* p) {
    uint32_t a;
    asm("{ .reg .u64 t; cvta.to.shared.u64 t, %1; cvt.u32.u64 %0, t; }"
        : "=r"(a) : "l"(p));
    return a;
}

__device__ __forceinline__ float fexp2(float x) {
    x = fmaxf(x, -120.f);
    float k = rintf(x);
    float r = x - k;
    float p = 0.0013333558f;
    p = fmaf(p, r, 0.0096181291f);
    p = fmaf(p, r, 0.0555041087f);
    p = fmaf(p, r, 0.2402265069f);
    p = fmaf(p, r, 0.6931471806f);
    p = fmaf(p, r, 1.0f);
    return p * __int_as_float(((int)k + 127) << 23);
}

__device__ __forceinline__ void load_tile_h(
    uint32_t sdst, const __half* __restrict__ src, long ld, int tid)
{
    #pragma unroll
    for (int i = 0; i < 8; i++) {
        int idx = tid + (i << 7);
        int r = idx >> 3;
        int c = idx & 7;
        uint32_t sw = (uint32_t)r * 128 + (uint32_t)((c ^ (r & 7)) << 4);
        asm volatile("cp.async.cg.shared.global [%0], [%1], 16;"
                     :: "r"(sdst + sw), "l"(src + (long)r * ld + (c << 3))
                     : "memory");
    }
}

#define LDSM4(r0, r1, r2, r3, a)                                           \
    asm volatile("ldmatrix.sync.aligned.m8n8.x4.shared.b16 {%0,%1,%2,%3}, [%4];" \
                 : "=r"(r0), "=r"(r1), "=r"(r2), "=r"(r3) : "r"(a))

#define MMA16816_H(acc, av, b0, b1)                                         \
    asm volatile(                                                           \
        "mma.sync.aligned.m16n8k16.row.col.f16.f16.f16.f16 "                \
        "{%0,%1}, {%2,%3,%4,%5}, {%6,%7}, {%0,%1};"                         \
        : "+r"((acc)[0]), "+r"((acc)[1])                                    \
        : "r"((av)[0]), "r"((av)[1]), "r"((av)[2]), "r"((av)[3]),           \
          "r"(b0), "r"(b1))

// 2-stage mainloop: load t+1 while computing t
#define GEMM_MAINLOOP2(MMA_OP, ACC)                                         \
    load_tile_h(sA[0], Ab, lda, tid);                                       \
    load_tile_h(sB[0], Bb, ldb, tid);                                       \
    asm volatile("cp.async.commit_group;");                                 \
    for (int t = 0; t < T; t++) {                                           \
        int cs = t & 1;                                                     \
        if (t + 1 < T) {                                                    \
            load_tile_h(sA[cs ^ 1], Ab + (size_t)(t + 1) * BK, lda, tid);   \
            load_tile_h(sB[cs ^ 1], Bb + (size_t)(t + 1) * BK, ldb, tid);   \
            asm volatile("cp.async.commit_group;");                         \
            asm volatile("cp.async.wait_group 1;");                         \
        } else {                                                            \
            asm volatile("cp.async.wait_group 0;");                         \
        }                                                                   \
        __syncthreads();                                                    \
        _Pragma("unroll")                                                   \
        for (int ks = 0; ks < 4; ks++) {                                    \
            int ach = ks * 2 + a_cs;                                        \
            int bch = ks * 2 + b_cs;                                        \
            uint32_t b0[4], b1[4];                                          \
            {                                                               \
                uint32_t row = bRow;                                        \
                uint32_t addr = sB[cs] + row * 128                          \
                              + (uint32_t)((bch ^ (row & 7)) << 4);         \
                LDSM4(b0[0], b0[1], b0[2], b0[3], addr);                    \
            }                                                               \
            uint32_t a[4][4];                                               \
            _Pragma("unroll")                                               \
            for (int mt = 0; mt < 4; mt++) {                                \
                uint32_t row = aRow + mt * 16;                              \
                uint32_t addr = sA[cs] + row * 128                          \
                              + (uint32_t)((ach ^ (row & 7)) << 4);         \
                LDSM4(a[mt][0], a[mt][1], a[mt][2], a[mt][3], addr);        \
            }                                                               \
            _Pragma("unroll")                                               \
            for (int p = 0; p < 4; p++) {                                   \
                uint32_t* bc = (p & 1) ? b1 : b0;                           \
                uint32_t* bn = (p & 1) ? b0 : b1;                           \
                if (p < 3) {                                                \
                    uint32_t row = bRow + (p + 1) * 16;                     \
                    uint32_t addr = sB[cs] + row * 128                      \
                                  + (uint32_t)((bch ^ (row & 7)) << 4);     \
                    LDSM4(bn[0], bn[1], bn[2], bn[3], addr);                \
                }                                                           \
                _Pragma("unroll")                                           \
                for (int mt = 0; mt < 4; mt++) {                            \
                    MMA_OP(ACC[mt][2 * p],     a[mt], bc[0], bc[1]);        \
                    MMA_OP(ACC[mt][2 * p + 1], a[mt], bc[2], bc[3]);        \
                }                                                           \
            }                                                               \
        }                                                                   \
        __syncthreads();                                                    \
    }

// common prologue for both kernels
#define GEMM_PROLOGUE()                                                     \
    extern __shared__ __half smem[];                                        \
    uint32_t sb = smem_u32(smem);                                           \
    uint32_t sA[2], sB[2];                                                  \
    _Pragma("unroll")                                                       \
    for (int s = 0; s < 2; s++) {                                           \
        sA[s] = sb + (uint32_t)s * 2 * STAGE_B;                             \
        sB[s] = sA[s] + STAGE_B;                                            \
    }                                                                       \
    int tid = threadIdx.x, lane = tid & 31, wid = tid >> 5;                 \
    int wm = wid >> 1, wn = wid & 1;                                        \
    int m0 = blockIdx.y * BM, n0 = blockIdx.x * BN;                         \
    const __half* Ab = A + (size_t)m0 * lda;                                \
    const __half* Bb = Bp + (size_t)n0 * ldb;                               \
    uint32_t acc[4][8][2];                                                  \
    _Pragma("unroll")                                                       \
    for (int i = 0; i < 4; i++)                                             \
        _Pragma("unroll")                                                   \
        for (int j = 0; j < 8; j++) { acc[i][j][0] = 0u; acc[i][j][1] = 0u; }\
    int a_r  = (lane & 7) | (((lane >> 3) & 1) << 3);                       \
    int a_cs = lane >> 4;                                                   \
    int b_r  = (lane & 7) | (((lane >> 4) & 1) << 3);                       \
    int b_cs = (lane >> 3) & 1;                                             \
    uint32_t aRow = (uint32_t)(wm * 64 + a_r);                              \
    uint32_t bRow = (uint32_t)(wn * 64 + b_r);

// ================= fp16-acc GEMM (QK / V / scores / PV) ====================
// emode: 0 = bias, 1 = exp2 + atomic rowsum, 2 = divide by rowsum
__global__ __launch_bounds__(128, 3) void mm_h16(
    const __half* __restrict__ A, long lda,
    const __half* __restrict__ Bp, long ldb,
    __half* __restrict__ Ch, long ldc,
    const float* __restrict__ bias_m, const float* __restrict__ bias_n,
    float alpha, int T, float* __restrict__ rowsum, int emode)
{
    GEMM_PROLOGUE()
    GEMM_MAINLOOP2(MMA16816_H, acc)

    int mb = m0 + wm * 64;
    int nb = n0 + wn * 64;
    int r0 = lane >> 2, c0 = (lane & 3) * 2;

    #pragma unroll
    for (int mt = 0; mt < 4; mt++) {
        #pragma unroll
        for (int h = 0; h < 2; h++) {
            int m = mb + mt * 16 + r0 + h * 8;
            float bmv = bias_m ? bias_m[m] : 0.f;
            float inv = 1.0f;
            if (emode == 2) inv = 1.0f / rowsum[m];
            float rsum = 0.f;
            #pragma unroll
            for (int nt = 0; nt < 8; nt++) {
                int n = nb + nt * 8 + c0;
                float2 f = __half22float2(
                    *reinterpret_cast<__half2*>(&acc[mt][nt][h]));
                float v0 = f.x, v1 = f.y;
                if (emode == 1) {
                    v0 = fexp2(v0 * alpha);
                    v1 = fexp2(v1 * alpha);
                    rsum += v0 + v1;
                } else if (emode == 2) {
                    v0 *= inv; v1 *= inv;
                } else {
                    v0 += bmv; v1 += bmv;
                    if (bias_n) { v0 += bias_n[n]; v1 += bias_n[n + 1]; }
                }
                *reinterpret_cast<__half2*>(Ch + (size_t)m * ldc + n) =
                    __floats2half2_rn(v0, v1);
            }
            if (emode == 1) {
                rsum += __shfl_xor_sync(0xffffffffu, rsum, 1);
                rsum += __shfl_xor_sync(0xffffffffu, rsum, 2);
                if ((lane & 3) == 0) atomicAdd(&rowsum[m], rsum);
            }
        }
    }
}

// ====== fp16-acc GEMM, final conv: bias + residual(fp32) + fp32 out ========
__global__ __launch_bounds__(128, 3) void mm_h16f(
    const __half* __restrict__ A, long lda,
    const __half* __restrict__ Bp, long ldb,
    float* __restrict__ Cf, long ldc,
    const float* __restrict__ bias_m,
    const float* __restrict__ res, float alpha, int T)
{
    GEMM_PROLOGUE()
    GEMM_MAINLOOP2(MMA16816_H, acc)

    int mb = m0 + wm * 64;
    int nb = n0 + wn * 64;
    int r0 = lane >> 2, c0 = (lane & 3) * 2;

    #pragma unroll
    for (int mt = 0; mt < 4; mt++) {
        #pragma unroll
        for (int h = 0; h < 2; h++) {
            int m = mb + mt * 16 + r0 + h * 8;
            float bmv = bias_m[m];
            #pragma unroll
            for (int nt = 0; nt < 8; nt++) {
                int n = nb + nt * 8 + c0;
                float2 f = __half22float2(
                    *reinterpret_cast<__half2*>(&acc[mt][nt][h]));
                const float* rp = res + (size_t)m * ldc + n;
                float v0 = (f.x + bmv + rp[0]) * alpha;
                float v1 = (f.y + bmv + rp[1]) * alpha;
                *reinterpret_cast<float2*>(Cf + (size_t)m * ldc + n) =
                    make_float2(v0, v1);
            }
        }
    }
}

// ============================ Launcher =====================================
extern "C" void kernel_launch(void* const* d_in, const int* in_sizes, int n_in,
                              void* d_out, int out_size)
{
    const float* q     = (const float*)d_in[0];
    const float* gamma = (const float*)d_in[1];
    const float* beta  = (const float*)d_in[2];
    const float* wq    = (const float*)d_in[3];
    const float* bq    = (const float*)d_in[4];
    const float* wk    = (const float*)d_in[5];
    const float* bk    = (const float*)d_in[6];
    const float* wv    = (const float*)d_in[7];
    const float* bv    = (const float*)d_in[8];
    const float* wo    = (const float*)d_in[9];
    const float* bo    = (const float*)d_in[10];
    float* out = (float*)d_out;

    __half *xt, *qk, *v, *st, *ot, *wh;
    float *bqk, *rsum;
    cudaGetSymbolAddress((void**)&xt, g_xt);
    cudaGetSymbolAddress((void**)&qk, g_qk);
    cudaGetSymbolAddress((void**)&v,  g_v);
    cudaGetSymbolAddress((void**)&st, g_st);
    cudaGetSymbolAddress((void**)&ot, g_ot);
    cudaGetSymbolAddress((void**)&wh, g_wh);
    cudaGetSymbolAddress((void**)&bqk, g_bqk);
    cudaGetSymbolAddress((void**)&rsum, g_rsum);
    __half* wqh = wh;
    __half* wvh = wh + 2 * (size_t)C_ * C_;
    __half* woh = wh + 3 * (size_t)C_ * C_;

    static int inited = 0;
    static cudaStream_t sx[B_ - 1];
    static cudaEvent_t efork0, eprep, ejoin[B_ - 1];
    if (!inited) {
        cudaFuncSetAttribute(mm_h16,
                             cudaFuncAttributeMaxDynamicSharedMemorySize,
                             SMEM_SZ);
        cudaFuncSetAttribute(mm_h16f,
                             cudaFuncAttributeMaxDynamicSharedMemorySize,
                             SMEM_SZ);
        for (int i = 0; i < B_ - 1; i++)
            cudaStreamCreateWithFlags(&sx[i], cudaStreamNonBlocking);
        cudaEventCreateWithFlags(&efork0, cudaEventDisableTiming);
        cudaEventCreateWithFlags(&eprep, cudaEventDisableTiming);
        for (int i = 0; i < B_ - 1; i++)
            cudaEventCreateWithFlags(&ejoin[i], cudaEventDisableTiming);
        inited = 1;
    }

    const size_t CB  = (size_t)C_ * HW_;
    const size_t QKB = (size_t)HW_ * 1024;
    const size_t SB  = (size_t)HW_ * HW_;
    const float SCALE2 = 0.044194173824159216f * 1.4426950408889634f;

    // ---- fork all side streams from the captured origin FIRST ----
    cudaEventRecord(efork0, 0);
    for (int i = 0; i < B_ - 1; i++) cudaStreamWaitEvent(sx[i], efork0, 0);

    // prep on stream 0 (weights/bias/rowsum); eprep gates every QK launch
    int prep_n = 4 * C_ * C_ / 4 + 1024 + B_ * HW_;
    prep_kernel<<<(prep_n + 255) / 256, 256>>>(wq, wk, wv, wo, wh,
                                               bq, bk, bqk, rsum);
    cudaEventRecord(eprep, 0);

    dim3 gQK(1024 / BN, HW_ / BM);   // (8, 32)
    dim3 gV(HW_ / BN, C_ / BM);      // (32, 4)
    dim3 gS(HW_ / BN, HW_ / BM);     // (32, 32)
    dim3 gP(C_ / BN, HW_ / BM);      // (4, 32)

    for (int b = 0; b < B_; b++) {
        cudaStream_t s = (b == 0) ? (cudaStream_t)0 : sx[b - 1];
        const float* qb = q + (size_t)b * CB;
        __half* xtb = xt + (size_t)b * CB;
        __half* qkb = qk + (size_t)b * QKB;
        __half* vb  = v  + (size_t)b * CB;
        __half* stb = st + (size_t)b * SB;
        __half* otb = ot + (size_t)b * CB;
        float*  rsb = rsum + (size_t)b * HW_;
        float* outb = out + (size_t)b * CB;

        // per-batch GroupNorm (independent of prep)
        gn_fused_b<<<NG_, 256, 0, s>>>(qb, gamma, beta, xtb);

        // weights required from here on
        if (b != 0) cudaStreamWaitEvent(s, eprep, 0);

        mm_h16<<<gQK, 128, SMEM_SZ, s>>>(xtb, C_,  wqh, C_,
                                         qkb, 1024,
                                         nullptr, bqk, 1.0f, C_ / BK,
                                         nullptr, 0);
        mm_h16<<<gV, 128, SMEM_SZ, s>>>(wvh, C_,  xtb, C_,
                                        vb, HW_,
                                        bv, nullptr, 1.0f, C_ / BK,
                                        nullptr, 0);
        mm_h16<<<gS, 128, SMEM_SZ, s>>>(qkb, 1024,  qkb + 512, 1024,
                                        stb, HW_,
                                        nullptr, nullptr, SCALE2, C_ / BK,
                                        rsb, 1);
        mm_h16<<<gP, 128, SMEM_SZ, s>>>(stb, HW_,  vb, HW_,
                                        otb, C_,
                                        nullptr, nullptr, 1.0f, HW_ / BK,
                                        rsb, 2);
        mm_h16f<<<gV, 128, SMEM_SZ, s>>>(woh, C_,  otb, C_,
                                         outb, HW_,
                                         bo, qb, 0.7071067811865476f,
                                         C_ / BK);
    }

    // ---- join ----
    for (int i = 0; i < B_ - 1; i++) {
        cudaEventRecord(ejoin[i], sx[i]);
        cudaStreamWaitEvent(0, ejoin[i], 0);
    }
}